// round 13
// baseline (speedup 1.0000x reference)
#include <cuda_runtime.h>
#include <cuda_bf16.h>
#include <cuda_fp16.h>
#include <cstdint>

#define NN 50000
#define NE 800000
#define DI 64
#define DE 32
#define DH 128
#define TE 64
#define THREADS 128
#define NTILES (NE / TE)   // 12500

// row strides in BYTES
#define A_STRB  80
#define W1_STRB 272
#define W2_STRB 144

// ---------------- scratch ----------------
__device__ __half   g_msg[(size_t)NE * DI];   // fp16 messages, 102 MB
__device__ float    g_scores[NE];
__device__ float    g_scoreS[NE];             // scores in CSR order
__device__ int      g_csr[NE];                // edge ids in CSR order
__device__ int      g_off[NN + 1];
__device__ int      g_cnt[NN];
__device__ int      g_cnt2[NN];

__device__ __forceinline__ uint32_t smem_u32(const void* p) {
    uint32_t a;
    asm("{ .reg .u64 t; cvta.to.shared.u64 t, %1; cvt.u32.u64 %0, t; }" : "=r"(a) : "l"(p));
    return a;
}
__device__ __forceinline__ uint32_t pk2(__nv_bfloat16 a, __nv_bfloat16 b) {
    __nv_bfloat162 t; t.x = a; t.y = b;
    return *reinterpret_cast<uint32_t*>(&t);
}
__device__ __forceinline__ uint32_t pk2f(float a, float b) {
    return pk2(__float2bfloat16_rn(a), __float2bfloat16_rn(b));
}
__device__ __forceinline__ float bl(float v) {          // lo residual
    return v - __bfloat162float(__float2bfloat16_rn(v));
}
__device__ __forceinline__ float tanh_fast(float v) {
    v = fminf(fmaxf(v, -20.f), 20.f);
    float e = __expf(2.f * v);
    return 1.f - __fdividef(2.f, e + 1.f);
}

#define LDSM_X4(r0, r1, r2, r3, addr) \
    asm volatile("ldmatrix.sync.aligned.m8n8.x4.shared.b16 {%0,%1,%2,%3}, [%4];" \
        : "=r"(r0), "=r"(r1), "=r"(r2), "=r"(r3) : "r"(addr))

#define LDSM_X4T(r0, r1, r2, r3, addr) \
    asm volatile("ldmatrix.sync.aligned.m8n8.x4.trans.shared.b16 {%0,%1,%2,%3}, [%4];" \
        : "=r"(r0), "=r"(r1), "=r"(r2), "=r"(r3) : "r"(addr))

#define MMA16816(d, a0, a1, a2, a3, b0, b1) \
    asm volatile("mma.sync.aligned.m16n8k16.row.col.f32.bf16.bf16.f32 " \
        "{%0,%1,%2,%3}, {%4,%5,%6,%7}, {%8,%9}, {%0,%1,%2,%3};" \
        : "+f"((d)[0]), "+f"((d)[1]), "+f"((d)[2]), "+f"((d)[3]) \
        : "r"(a0), "r"(a1), "r"(a2), "r"(a3), "r"(b0), "r"(b1))

// ---- smem layout (bytes) ----
#define S_SRC   0
#define S_TGT   256
#define S_B1    512
#define S_B2    1024
#define S_AV    1280
#define S_AH    1536        // 64 x 80B = 5120
#define S_AL    6656
#define S_W1H   11776       // 32 x 272B = 8704
#define S_W1L   20480
#define S_W2H   29184       // 128 x 144B = 18432
#define S_W2L   47616
#define S_TOTAL 66048

// ---------------- K0: zero histogram counters ----------------
__global__ void k0_init() {
    int i = blockIdx.x * blockDim.x + threadIdx.x;
    if (i < NN) { g_cnt[i] = 0; g_cnt2[i] = 0; }
}

// ---------------- K1: persistent mma.sync bf16x3, 2 CTAs/SM, fp16 msg ----------------
__global__ void __launch_bounds__(THREADS, 2) k1_mma(
    const float* __restrict__ x,  const int*   __restrict__ ei,
    const float* __restrict__ ea, const float* __restrict__ W1,
    const float* __restrict__ b1, const float* __restrict__ W2,
    const float* __restrict__ b2, const float* __restrict__ av)
{
    extern __shared__ char smem[];
    const uint32_t sb = smem_u32(smem);
    const int tid = threadIdx.x;
    const int wid = tid >> 5;
    const int lid = tid & 31;
    const int rw  = wid * 16;

    float* sf   = reinterpret_cast<float*>(smem);
    int*   sSrc = reinterpret_cast<int*>(smem + S_SRC);
    int*   sTgt = reinterpret_cast<int*>(smem + S_TGT);
    float* sB1  = sf + (S_B1 >> 2);
    float* sB2  = sf + (S_B2 >> 2);
    float* sAV  = sf + (S_AV >> 2);

    if (tid < DH) sB1[tid] = b1[tid];
    if (tid < DI) { sB2[tid] = b2[tid]; sAV[tid] = av[tid]; }

    for (int idx = tid; idx < DE * DH; idx += THREADS) {        // W1 [32][128]
        int k = idx >> 7, n = idx & 127;
        float v = __ldg(W1 + k * DH + n);
        __nv_bfloat16 h = __float2bfloat16_rn(v);
        __nv_bfloat16 l = __float2bfloat16_rn(v - __bfloat162float(h));
        *reinterpret_cast<__nv_bfloat16*>(smem + S_W1H + k * W1_STRB + n * 2) = h;
        *reinterpret_cast<__nv_bfloat16*>(smem + S_W1L + k * W1_STRB + n * 2) = l;
    }
    for (int idx = tid; idx < DH * DI; idx += THREADS) {        // W2 [128][64]
        int k = idx >> 6, n = idx & 63;
        float v = __ldg(W2 + k * DI + n);
        __nv_bfloat16 h = __float2bfloat16_rn(v);
        __nv_bfloat16 l = __float2bfloat16_rn(v - __bfloat162float(h));
        *reinterpret_cast<__nv_bfloat16*>(smem + S_W2H + k * W2_STRB + n * 2) = h;
        *reinterpret_cast<__nv_bfloat16*>(smem + S_W2L + k * W2_STRB + n * 2) = l;
    }

    uint2 pfh[4], pfl[4];
    int pfsrc = 0, pftgt = 0;

    #define LOAD_TILE(TILE) do {                                               \
        int _e0 = (TILE) * TE;                                                 \
        _Pragma("unroll")                                                      \
        for (int _i = 0; _i < 4; _i++) {                                       \
            int _idx4 = tid + _i * THREADS;                                    \
            int _e = _idx4 >> 3, _q = _idx4 & 7;                               \
            float4 _v = __ldg(reinterpret_cast<const float4*>(                 \
                ea + (size_t)(_e0 + _e) * DE + _q * 4));                       \
            pfh[_i] = make_uint2(pk2f(_v.x, _v.y), pk2f(_v.z, _v.w));          \
            pfl[_i] = make_uint2(pk2f(bl(_v.x), bl(_v.y)),                     \
                                 pk2f(bl(_v.z), bl(_v.w)));                    \
        }                                                                      \
        if (tid < TE) {                                                        \
            pfsrc = __ldg(ei + _e0 + tid);                                     \
            pftgt = __ldg(ei + NE + _e0 + tid);                                \
        }                                                                      \
    } while (0)

    if (blockIdx.x < NTILES) LOAD_TILE(blockIdx.x);
    __syncthreads();

    for (int tile = blockIdx.x; tile < NTILES; tile += gridDim.x) {
        const int e0 = tile * TE;

        #pragma unroll
        for (int i = 0; i < 4; i++) {
            int idx4 = tid + i * THREADS;
            int e = idx4 >> 3, q = idx4 & 7;
            *reinterpret_cast<uint2*>(smem + S_AH + e * A_STRB + q * 8) = pfh[i];
            *reinterpret_cast<uint2*>(smem + S_AL + e * A_STRB + q * 8) = pfl[i];
        }
        if (tid < TE) { sSrc[tid] = pfsrc; sTgt[tid] = pftgt; }
        __syncthreads();

        {
            int nxt = tile + gridDim.x;
            if (nxt < NTILES) LOAD_TILE(nxt);
        }

        // ---- GEMM1 ----
        float acc1[16][4];
        #pragma unroll
        for (int nt = 0; nt < 16; nt++)
            #pragma unroll
            for (int i = 0; i < 4; i++) acc1[nt][i] = 0.f;

        #pragma unroll
        for (int ks = 0; ks < 2; ks++) {
            uint32_t ah0, ah1, ah2, ah3, al0, al1, al2, al3;
            uint32_t aoff = (uint32_t)((rw + (lid & 15)) * A_STRB + ks * 32 + (lid >> 4) * 16);
            LDSM_X4(ah0, ah1, ah2, ah3, sb + S_AH + aoff);
            LDSM_X4(al0, al1, al2, al3, sb + S_AL + aoff);
            #pragma unroll
            for (int nt2 = 0; nt2 < 8; nt2++) {
                uint32_t koff = (uint32_t)((ks * 16 + (lid & 15)) * W1_STRB
                                           + (nt2 * 16 + (lid >> 4) * 8) * 2);
                uint32_t bh0, bh1, bh2, bh3, bl0, bl1, bl2, bl3;
                LDSM_X4T(bh0, bh1, bh2, bh3, sb + S_W1H + koff);
                LDSM_X4T(bl0, bl1, bl2, bl3, sb + S_W1L + koff);
                MMA16816(acc1[2 * nt2],     ah0, ah1, ah2, ah3, bh0, bh1);
                MMA16816(acc1[2 * nt2],     al0, al1, al2, al3, bh0, bh1);
                MMA16816(acc1[2 * nt2],     ah0, ah1, ah2, ah3, bl0, bl1);
                MMA16816(acc1[2 * nt2 + 1], ah0, ah1, ah2, ah3, bh2, bh3);
                MMA16816(acc1[2 * nt2 + 1], al0, al1, al2, al3, bh2, bh3);
                MMA16816(acc1[2 * nt2 + 1], ah0, ah1, ah2, ah3, bl2, bl3);
            }
        }

        // ---- tanh -> bf16 hi/lo A-fragments ----
        uint32_t hiA[16][2], loA[16][2];
        #pragma unroll
        for (int nt = 0; nt < 16; nt++) {
            int c0 = nt * 8 + (lid & 3) * 2;
            float bb0 = sB1[c0], bb1 = sB1[c0 + 1];
            float t0 = tanh_fast(acc1[nt][0] + bb0);
            float t1 = tanh_fast(acc1[nt][1] + bb1);
            float t2 = tanh_fast(acc1[nt][2] + bb0);
            float t3 = tanh_fast(acc1[nt][3] + bb1);
            hiA[nt][0] = pk2f(t0, t1);
            hiA[nt][1] = pk2f(t2, t3);
            loA[nt][0] = pk2f(bl(t0), bl(t1));
            loA[nt][1] = pk2f(bl(t2), bl(t3));
        }

        // ---- GEMM2 ----
        float acc2[8][4];
        #pragma unroll
        for (int nt = 0; nt < 8; nt++)
            #pragma unroll
            for (int i = 0; i < 4; i++) acc2[nt][i] = 0.f;

        #pragma unroll
        for (int ks = 0; ks < 8; ks++) {
            uint32_t ah0 = hiA[2 * ks][0],     ah1 = hiA[2 * ks][1];
            uint32_t ah2 = hiA[2 * ks + 1][0], ah3 = hiA[2 * ks + 1][1];
            uint32_t al0 = loA[2 * ks][0],     al1 = loA[2 * ks][1];
            uint32_t al2 = loA[2 * ks + 1][0], al3 = loA[2 * ks + 1][1];
            #pragma unroll
            for (int nt2 = 0; nt2 < 4; nt2++) {
                uint32_t koff = (uint32_t)((ks * 16 + (lid & 15)) * W2_STRB
                                           + (nt2 * 16 + (lid >> 4) * 8) * 2);
                uint32_t bh0, bh1, bh2, bh3, bl0, bl1, bl2, bl3;
                LDSM_X4T(bh0, bh1, bh2, bh3, sb + S_W2H + koff);
                LDSM_X4T(bl0, bl1, bl2, bl3, sb + S_W2L + koff);
                MMA16816(acc2[2 * nt2],     ah0, ah1, ah2, ah3, bh0, bh1);
                MMA16816(acc2[2 * nt2],     al0, al1, al2, al3, bh0, bh1);
                MMA16816(acc2[2 * nt2],     ah0, ah1, ah2, ah3, bl0, bl1);
                MMA16816(acc2[2 * nt2 + 1], ah0, ah1, ah2, ah3, bh2, bh3);
                MMA16816(acc2[2 * nt2 + 1], al0, al1, al2, al3, bh2, bh3);
                MMA16816(acc2[2 * nt2 + 1], ah0, ah1, ah2, ah3, bl2, bl3);
            }
        }

        // ---- epilogue: fp16 streaming msg store + scores + histogram ----
        {
            const int j2 = (lid & 3) * 2;
            const int r0 = rw + (lid >> 2);
            const int r1 = r0 + 8;
            const int src0 = sSrc[r0], src1 = sSrc[r1];
            const float* x0 = x + (size_t)src0 * DI;
            const float* x1 = x + (size_t)src1 * DI;
            __half2* m0 = reinterpret_cast<__half2*>(g_msg + (size_t)(e0 + r0) * DI);
            __half2* m1 = reinterpret_cast<__half2*>(g_msg + (size_t)(e0 + r1) * DI);
            float p0 = 0.f, p1 = 0.f;
            #pragma unroll
            for (int nt = 0; nt < 8; nt++) {
                int c0 = nt * 8 + j2;
                float bb0 = sB2[c0], bb1 = sB2[c0 + 1];
                float vv0 = sAV[c0], vv1 = sAV[c0 + 1];
                float2 xv0 = __ldg(reinterpret_cast<const float2*>(x0 + c0));
                float2 xv1 = __ldg(reinterpret_cast<const float2*>(x1 + c0));
                float a0 = xv0.x * (acc2[nt][0] + bb0);
                float a1 = xv0.y * (acc2[nt][1] + bb1);
                float b0 = xv1.x * (acc2[nt][2] + bb0);
                float b1 = xv1.y * (acc2[nt][3] + bb1);
                __stcs(m0 + (c0 >> 1), __floats2half2_rn(a0, a1));
                __stcs(m1 + (c0 >> 1), __floats2half2_rn(b0, b1));
                p0 += a0 * vv0 + a1 * vv1;
                p1 += b0 * vv0 + b1 * vv1;
            }
            p0 += __shfl_xor_sync(0xFFFFFFFFu, p0, 1);
            p0 += __shfl_xor_sync(0xFFFFFFFFu, p0, 2);
            p1 += __shfl_xor_sync(0xFFFFFFFFu, p1, 1);
            p1 += __shfl_xor_sync(0xFFFFFFFFu, p1, 2);
            if ((lid & 3) == 0) {
                g_scores[e0 + r0] = p0;
                atomicAdd(&g_cnt[sTgt[r0]], 1);
                g_scores[e0 + r1] = p1;
                atomicAdd(&g_cnt[sTgt[r1]], 1);
            }
        }
        __syncthreads();
    }
    #undef LOAD_TILE
}

// ---------------- K2: exclusive scan of histogram (single block) ----------------
#define CHUNK 49   // 1024 * 49 = 50176 >= NN
__global__ void k2_scan() {
    __shared__ int sm[1024];
    int tid = threadIdx.x;
    int base = tid * CHUNK;
    int s = 0;
    #pragma unroll 7
    for (int j = 0; j < CHUNK; j++) {
        int idx = base + j;
        if (idx < NN) s += g_cnt[idx];
    }
    sm[tid] = s;
    __syncthreads();
    for (int off = 1; off < 1024; off <<= 1) {
        int v = (tid >= off) ? sm[tid - off] : 0;
        __syncthreads();
        sm[tid] += v;
        __syncthreads();
    }
    int run = sm[tid] - s;     // exclusive prefix for this chunk
    #pragma unroll 7
    for (int j = 0; j < CHUNK; j++) {
        int idx = base + j;
        if (idx < NN) { g_off[idx] = run; run += g_cnt[idx]; }
    }
    if (tid == 0) g_off[NN] = NE;
}

// ---------------- K3: scatter edge ids + scores into CSR order ----------------
__global__ void k3_scatter_idx(const int* __restrict__ ei) {
    int e = blockIdx.x * blockDim.x + threadIdx.x;
    if (e >= NE) return;
    int tgt = ei[NE + e];
    int pos = g_off[tgt] + atomicAdd(&g_cnt2[tgt], 1);
    g_csr[pos]    = e;
    g_scoreS[pos] = g_scores[e];
}

// ---------------- K4: per-node softmax + gather (one warp per node) ----------------
__global__ void __launch_bounds__(256) k4_gather(float* __restrict__ out,
                                                 float* __restrict__ att) {
    int w    = (blockIdx.x * blockDim.x + threadIdx.x) >> 5;
    int lane = threadIdx.x & 31;
    if (w >= NN) return;
    int beg = g_off[w], end = g_off[w + 1];
    float2 acc = make_float2(0.f, 0.f);
    if (end > beg) {
        float mx = -1e30f;
        for (int i = beg + lane; i < end; i += 32) mx = fmaxf(mx, g_scoreS[i]);
        #pragma unroll
        for (int o = 16; o; o >>= 1) mx = fmaxf(mx, __shfl_xor_sync(0xFFFFFFFFu, mx, o));
        float den = 0.f;
        for (int i = beg + lane; i < end; i += 32) den += __expf(g_scoreS[i] - mx);
        #pragma unroll
        for (int o = 16; o; o >>= 1) den += __shfl_xor_sync(0xFFFFFFFFu, den, o);
        float rden = __fdividef(1.f, den);
        for (int i = beg; i < end; i++) {
            int e = g_csr[i];
            float aw = __expf(g_scoreS[i] - mx) * rden;
            __half2 m = *reinterpret_cast<const __half2*>(g_msg + (size_t)e * DI + lane * 2);
            float2 mf = __half22float2(m);
            acc.x = fmaf(aw, mf.x, acc.x);
            acc.y = fmaf(aw, mf.y, acc.y);
            if (lane == 0) att[e] = aw;
        }
    }
    *reinterpret_cast<float2*>(out + (size_t)w * DI + lane * 2) = acc;
}

// ---------------- launch ----------------
extern "C" void kernel_launch(void* const* d_in, const int* in_sizes, int n_in,
                              void* d_out, int out_size) {
    const float* x  = (const float*)d_in[0];
    const int*   ei = (const int*)  d_in[1];
    const float* ea = (const float*)d_in[2];
    const float* W1 = (const float*)d_in[3];
    const float* b1 = (const float*)d_in[4];
    const float* W2 = (const float*)d_in[5];
    const float* b2 = (const float*)d_in[6];
    const float* av = (const float*)d_in[7];

    float* out = (float*)d_out;
    float* att = out + (size_t)NN * DI;

    cudaFuncSetAttribute(k1_mma, cudaFuncAttributeMaxDynamicSharedMemorySize, S_TOTAL);

    k0_init<<<(NN + 255) / 256, 256>>>();
    k1_mma<<<296, THREADS, S_TOTAL>>>(x, ei, ea, W1, b1, W2, b2, av);
    k2_scan<<<1, 1024>>>();
    k3_scatter_idx<<<(NE + 255) / 256, 256>>>(ei);
    k4_gather<<<(NN * 32 + 255) / 256, 256>>>(out, att);
}

// round 15
// speedup vs baseline: 1.1835x; 1.1835x over previous
#include <cuda_runtime.h>
#include <cuda_bf16.h>
#include <cuda_fp16.h>
#include <cstdint>

#define NN 50000
#define NE 800000
#define DI 64
#define DE 32
#define DH 128
#define TE 64
#define THREADS 128
#define NTILES (NE / TE)   // 12500

// row strides in BYTES
#define A_STRB  80
#define W1_STRB 272
#define W2_STRB 144

// ---------------- scratch ----------------
__device__ __half   g_msg[(size_t)NE * DI];   // fp16 messages, 102 MB
__device__ float    g_scores[NE];
__device__ float    g_ex[NE];
__device__ unsigned g_segmax[NN];
__device__ float    g_denom[NN];

__device__ __forceinline__ unsigned enc_f(float f) {
    unsigned u = __float_as_uint(f);
    return (u & 0x80000000u) ? ~u : (u | 0x80000000u);
}
__device__ __forceinline__ float dec_f(unsigned u) {
    return (u & 0x80000000u) ? __uint_as_float(u & 0x7FFFFFFFu)
                             : __uint_as_float(~u);
}

__device__ __forceinline__ uint32_t smem_u32(const void* p) {
    uint32_t a;
    asm("{ .reg .u64 t; cvta.to.shared.u64 t, %1; cvt.u32.u64 %0, t; }" : "=r"(a) : "l"(p));
    return a;
}
__device__ __forceinline__ uint32_t pk2(__nv_bfloat16 a, __nv_bfloat16 b) {
    __nv_bfloat162 t; t.x = a; t.y = b;
    return *reinterpret_cast<uint32_t*>(&t);
}
__device__ __forceinline__ uint32_t pk2f(float a, float b) {
    return pk2(__float2bfloat16_rn(a), __float2bfloat16_rn(b));
}
__device__ __forceinline__ float bl(float v) {          // lo residual
    return v - __bfloat162float(__float2bfloat16_rn(v));
}
__device__ __forceinline__ float tanh_fast(float v) {   // unclamped: inf path -> ±1
    float e = __expf(2.f * v);
    return 1.f - __fdividef(2.f, e + 1.f);
}

#define LDSM_X4(r0, r1, r2, r3, addr) \
    asm volatile("ldmatrix.sync.aligned.m8n8.x4.shared.b16 {%0,%1,%2,%3}, [%4];" \
        : "=r"(r0), "=r"(r1), "=r"(r2), "=r"(r3) : "r"(addr))

#define LDSM_X4T(r0, r1, r2, r3, addr) \
    asm volatile("ldmatrix.sync.aligned.m8n8.x4.trans.shared.b16 {%0,%1,%2,%3}, [%4];" \
        : "=r"(r0), "=r"(r1), "=r"(r2), "=r"(r3) : "r"(addr))

#define MMA16816(d, a0, a1, a2, a3, b0, b1) \
    asm volatile("mma.sync.aligned.m16n8k16.row.col.f32.bf16.bf16.f32 " \
        "{%0,%1,%2,%3}, {%4,%5,%6,%7}, {%8,%9}, {%0,%1,%2,%3};" \
        : "+f"((d)[0]), "+f"((d)[1]), "+f"((d)[2]), "+f"((d)[3]) \
        : "r"(a0), "r"(a1), "r"(a2), "r"(a3), "r"(b0), "r"(b1))

// ---- smem layout (bytes); A tile + src/tgt are DOUBLE-BUFFERED ----
#define S_SRC   0           // 2 x 64 ints  (buf stride 256)
#define S_TGT   512         // 2 x 64 ints
#define S_B1    1024
#define S_B2    1536
#define S_AV    1792
#define S_AH    2048        // 2 x (64 x 80B = 5120); AH0 2048, AL0 7168, AH1 12288, AL1 17408
#define S_AL    7168
#define A_BUFSTR 10240      // byte stride between buffer pairs
#define S_W1H   22528       // 32 x 272B = 8704
#define S_W1L   31232
#define S_W2H   39936       // 128 x 144B = 18432
#define S_W2L   58368
#define S_TOTAL 76800

// ---------------- K0 ----------------
__global__ void k0_init(float* __restrict__ out) {
    int i = blockIdx.x * blockDim.x + threadIdx.x;
    if (i < NN * DI) out[i] = 0.f;
    if (i < NN) { g_segmax[i] = 0u; g_denom[i] = 0.f; }
}

// ---------------- K1: persistent mma.sync bf16x3, 2 CTAs/SM, ping-pong A ----------------
__global__ void __launch_bounds__(THREADS, 2) k1_mma(
    const float* __restrict__ x,  const int*   __restrict__ ei,
    const float* __restrict__ ea, const float* __restrict__ W1,
    const float* __restrict__ b1, const float* __restrict__ W2,
    const float* __restrict__ b2, const float* __restrict__ av)
{
    extern __shared__ char smem[];
    const uint32_t sb = smem_u32(smem);
    const int tid = threadIdx.x;
    const int wid = tid >> 5;
    const int lid = tid & 31;
    const int rw  = wid * 16;

    float* sf   = reinterpret_cast<float*>(smem);
    float* sB1  = sf + (S_B1 >> 2);
    float* sB2  = sf + (S_B2 >> 2);
    float* sAV  = sf + (S_AV >> 2);

    if (tid < DH) sB1[tid] = b1[tid];
    if (tid < DI) { sB2[tid] = b2[tid]; sAV[tid] = av[tid]; }

    for (int idx = tid; idx < DE * DH; idx += THREADS) {        // W1 [32][128]
        int k = idx >> 7, n = idx & 127;
        float v = __ldg(W1 + k * DH + n);
        __nv_bfloat16 h = __float2bfloat16_rn(v);
        __nv_bfloat16 l = __float2bfloat16_rn(v - __bfloat162float(h));
        *reinterpret_cast<__nv_bfloat16*>(smem + S_W1H + k * W1_STRB + n * 2) = h;
        *reinterpret_cast<__nv_bfloat16*>(smem + S_W1L + k * W1_STRB + n * 2) = l;
    }
    for (int idx = tid; idx < DH * DI; idx += THREADS) {        // W2 [128][64]
        int k = idx >> 6, n = idx & 63;
        float v = __ldg(W2 + k * DI + n);
        __nv_bfloat16 h = __float2bfloat16_rn(v);
        __nv_bfloat16 l = __float2bfloat16_rn(v - __bfloat162float(h));
        *reinterpret_cast<__nv_bfloat16*>(smem + S_W2H + k * W2_STRB + n * 2) = h;
        *reinterpret_cast<__nv_bfloat16*>(smem + S_W2L + k * W2_STRB + n * 2) = l;
    }

    uint2 pfh[4], pfl[4];
    int pfsrc = 0, pftgt = 0;

    #define LOAD_TILE(TILE) do {                                               \
        int _e0 = (TILE) * TE;                                                 \
        _Pragma("unroll")                                                      \
        for (int _i = 0; _i < 4; _i++) {                                       \
            int _idx4 = tid + _i * THREADS;                                    \
            int _e = _idx4 >> 3, _q = _idx4 & 7;                               \
            float4 _v = __ldg(reinterpret_cast<const float4*>(                 \
                ea + (size_t)(_e0 + _e) * DE + _q * 4));                       \
            pfh[_i] = make_uint2(pk2f(_v.x, _v.y), pk2f(_v.z, _v.w));          \
            pfl[_i] = make_uint2(pk2f(bl(_v.x), bl(_v.y)),                     \
                                 pk2f(bl(_v.z), bl(_v.w)));                    \
        }                                                                      \
        if (tid < TE) {                                                        \
            pfsrc = __ldg(ei + _e0 + tid);                                     \
            pftgt = __ldg(ei + NE + _e0 + tid);                                \
        }                                                                      \
    } while (0)

    if (blockIdx.x < NTILES) LOAD_TILE(blockIdx.x);
    __syncthreads();

    int ic = 0;
    for (int tile = blockIdx.x; tile < NTILES; tile += gridDim.x, ic ^= 1) {
        const int e0 = tile * TE;
        const uint32_t abuf = (uint32_t)(ic * A_BUFSTR);
        int* sSrc = reinterpret_cast<int*>(smem + S_SRC + ic * 256);
        int* sTgt = reinterpret_cast<int*>(smem + S_TGT + ic * 256);

        // ---- commit prefetched tile to THIS iteration's buffer ----
        #pragma unroll
        for (int i = 0; i < 4; i++) {
            int idx4 = tid + i * THREADS;
            int e = idx4 >> 3, q = idx4 & 7;
            *reinterpret_cast<uint2*>(smem + S_AH + abuf + e * A_STRB + q * 8) = pfh[i];
            *reinterpret_cast<uint2*>(smem + S_AL + abuf + e * A_STRB + q * 8) = pfl[i];
        }
        if (tid < TE) { sSrc[tid] = pfsrc; sTgt[tid] = pftgt; }
        __syncthreads();                       // the ONLY sync per tile

        // ---- prefetch next tile (latency hidden behind GEMMs) ----
        {
            int nxt = tile + gridDim.x;
            if (nxt < NTILES) LOAD_TILE(nxt);
        }

        // ---- GEMM1 ----
        float acc1[16][4];
        #pragma unroll
        for (int nt = 0; nt < 16; nt++)
            #pragma unroll
            for (int i = 0; i < 4; i++) acc1[nt][i] = 0.f;

        #pragma unroll
        for (int ks = 0; ks < 2; ks++) {
            uint32_t ah0, ah1, ah2, ah3, al0, al1, al2, al3;
            uint32_t aoff = abuf + (uint32_t)((rw + (lid & 15)) * A_STRB + ks * 32 + (lid >> 4) * 16);
            LDSM_X4(ah0, ah1, ah2, ah3, sb + S_AH + aoff);
            LDSM_X4(al0, al1, al2, al3, sb + S_AL + aoff);
            #pragma unroll
            for (int nt2 = 0; nt2 < 8; nt2++) {
                uint32_t koff = (uint32_t)((ks * 16 + (lid & 15)) * W1_STRB
                                           + (nt2 * 16 + (lid >> 4) * 8) * 2);
                uint32_t bh0, bh1, bh2, bh3, bl0, bl1, bl2, bl3;
                LDSM_X4T(bh0, bh1, bh2, bh3, sb + S_W1H + koff);
                LDSM_X4T(bl0, bl1, bl2, bl3, sb + S_W1L + koff);
                MMA16816(acc1[2 * nt2],     ah0, ah1, ah2, ah3, bh0, bh1);
                MMA16816(acc1[2 * nt2],     al0, al1, al2, al3, bh0, bh1);
                MMA16816(acc1[2 * nt2],     ah0, ah1, ah2, ah3, bl0, bl1);
                MMA16816(acc1[2 * nt2 + 1], ah0, ah1, ah2, ah3, bh2, bh3);
                MMA16816(acc1[2 * nt2 + 1], al0, al1, al2, al3, bh2, bh3);
                MMA16816(acc1[2 * nt2 + 1], ah0, ah1, ah2, ah3, bl2, bl3);
            }
        }

        // ---- tanh -> bf16 hi/lo A-fragments ----
        uint32_t hiA[16][2], loA[16][2];
        #pragma unroll
        for (int nt = 0; nt < 16; nt++) {
            int c0 = nt * 8 + (lid & 3) * 2;
            float bb0 = sB1[c0], bb1 = sB1[c0 + 1];
            float t0 = tanh_fast(acc1[nt][0] + bb0);
            float t1 = tanh_fast(acc1[nt][1] + bb1);
            float t2 = tanh_fast(acc1[nt][2] + bb0);
            float t3 = tanh_fast(acc1[nt][3] + bb1);
            hiA[nt][0] = pk2f(t0, t1);
            hiA[nt][1] = pk2f(t2, t3);
            loA[nt][0] = pk2f(bl(t0), bl(t1));
            loA[nt][1] = pk2f(bl(t2), bl(t3));
        }

        // ---- GEMM2 ----
        float acc2[8][4];
        #pragma unroll
        for (int nt = 0; nt < 8; nt++)
            #pragma unroll
            for (int i = 0; i < 4; i++) acc2[nt][i] = 0.f;

        #pragma unroll
        for (int ks = 0; ks < 8; ks++) {
            uint32_t ah0 = hiA[2 * ks][0],     ah1 = hiA[2 * ks][1];
            uint32_t ah2 = hiA[2 * ks + 1][0], ah3 = hiA[2 * ks + 1][1];
            uint32_t al0 = loA[2 * ks][0],     al1 = loA[2 * ks][1];
            uint32_t al2 = loA[2 * ks + 1][0], al3 = loA[2 * ks + 1][1];
            #pragma unroll
            for (int nt2 = 0; nt2 < 4; nt2++) {
                uint32_t koff = (uint32_t)((ks * 16 + (lid & 15)) * W2_STRB
                                           + (nt2 * 16 + (lid >> 4) * 8) * 2);
                uint32_t bh0, bh1, bh2, bh3, bl0, bl1, bl2, bl3;
                LDSM_X4T(bh0, bh1, bh2, bh3, sb + S_W2H + koff);
                LDSM_X4T(bl0, bl1, bl2, bl3, sb + S_W2L + koff);
                MMA16816(acc2[2 * nt2],     ah0, ah1, ah2, ah3, bh0, bh1);
                MMA16816(acc2[2 * nt2],     al0, al1, al2, al3, bh0, bh1);
                MMA16816(acc2[2 * nt2],     ah0, ah1, ah2, ah3, bl0, bl1);
                MMA16816(acc2[2 * nt2 + 1], ah0, ah1, ah2, ah3, bh2, bh3);
                MMA16816(acc2[2 * nt2 + 1], al0, al1, al2, al3, bh2, bh3);
                MMA16816(acc2[2 * nt2 + 1], ah0, ah1, ah2, ah3, bl2, bl3);
            }
        }

        // ---- epilogue: fp16 streaming msg store + scores + segmax ----
        {
            const int j2 = (lid & 3) * 2;
            const int r0 = rw + (lid >> 2);
            const int r1 = r0 + 8;
            const int src0 = sSrc[r0], src1 = sSrc[r1];
            const float* x0 = x + (size_t)src0 * DI;
            const float* x1 = x + (size_t)src1 * DI;
            __half2* m0 = reinterpret_cast<__half2*>(g_msg + (size_t)(e0 + r0) * DI);
            __half2* m1 = reinterpret_cast<__half2*>(g_msg + (size_t)(e0 + r1) * DI);
            float p0 = 0.f, p1 = 0.f;
            #pragma unroll
            for (int nt = 0; nt < 8; nt++) {
                int c0 = nt * 8 + j2;
                float bb0 = sB2[c0], bb1 = sB2[c0 + 1];
                float vv0 = sAV[c0], vv1 = sAV[c0 + 1];
                float2 xv0 = __ldg(reinterpret_cast<const float2*>(x0 + c0));
                float2 xv1 = __ldg(reinterpret_cast<const float2*>(x1 + c0));
                float a0 = xv0.x * (acc2[nt][0] + bb0);
                float a1 = xv0.y * (acc2[nt][1] + bb1);
                float b0 = xv1.x * (acc2[nt][2] + bb0);
                float b1 = xv1.y * (acc2[nt][3] + bb1);
                __stcs(m0 + (c0 >> 1), __floats2half2_rn(a0, a1));
                __stcs(m1 + (c0 >> 1), __floats2half2_rn(b0, b1));
                p0 += a0 * vv0 + a1 * vv1;
                p1 += b0 * vv0 + b1 * vv1;
            }
            p0 += __shfl_xor_sync(0xFFFFFFFFu, p0, 1);
            p0 += __shfl_xor_sync(0xFFFFFFFFu, p0, 2);
            p1 += __shfl_xor_sync(0xFFFFFFFFu, p1, 1);
            p1 += __shfl_xor_sync(0xFFFFFFFFu, p1, 2);
            if ((lid & 3) == 0) {
                g_scores[e0 + r0] = p0;
                atomicMax(&g_segmax[sTgt[r0]], enc_f(p0));
                g_scores[e0 + r1] = p1;
                atomicMax(&g_segmax[sTgt[r1]], enc_f(p1));
            }
        }
        // no end-of-loop sync: next commit targets the other buffer
    }
    #undef LOAD_TILE
}

// ---------------- K2 ----------------
__global__ void k2_exp_denom(const int* __restrict__ ei) {
    int e = blockIdx.x * blockDim.x + threadIdx.x;
    if (e >= NE) return;
    int tgt = ei[NE + e];
    float ex = expf(g_scores[e] - dec_f(g_segmax[tgt]));
    g_ex[e] = ex;
    atomicAdd(&g_denom[tgt], ex);
}

// ---------------- K3: 8 threads/edge, fp16 msg read, v4 reductions ----------------
__global__ void k3_scatter(const int* __restrict__ ei,
                           float* __restrict__ out, float* __restrict__ att) {
    int t = blockIdx.x * blockDim.x + threadIdx.x;
    int e = t >> 3;
    if (e >= NE) return;
    int q   = t & 7;
    int tgt = ei[NE + e];
    float aw = g_ex[e] / g_denom[tgt];
    if (q == 0) att[e] = aw;
    const uint4 mv = __ldcs(reinterpret_cast<const uint4*>(g_msg + (size_t)e * DI) + q);
    const __half2* hp = reinterpret_cast<const __half2*>(&mv);
    float2 f0 = __half22float2(hp[0]);
    float2 f1 = __half22float2(hp[1]);
    float2 f2 = __half22float2(hp[2]);
    float2 f3 = __half22float2(hp[3]);
    float* addr = out + (size_t)tgt * DI + q * 8;
    asm volatile("red.global.add.v4.f32 [%0], {%1, %2, %3, %4};"
                 :: "l"(addr), "f"(f0.x * aw), "f"(f0.y * aw),
                    "f"(f1.x * aw), "f"(f1.y * aw) : "memory");
    asm volatile("red.global.add.v4.f32 [%0], {%1, %2, %3, %4};"
                 :: "l"(addr + 4), "f"(f2.x * aw), "f"(f2.y * aw),
                    "f"(f3.x * aw), "f"(f3.y * aw) : "memory");
}

// ---------------- launch ----------------
extern "C" void kernel_launch(void* const* d_in, const int* in_sizes, int n_in,
                              void* d_out, int out_size) {
    const float* x  = (const float*)d_in[0];
    const int*   ei = (const int*)  d_in[1];
    const float* ea = (const float*)d_in[2];
    const float* W1 = (const float*)d_in[3];
    const float* b1 = (const float*)d_in[4];
    const float* W2 = (const float*)d_in[5];
    const float* b2 = (const float*)d_in[6];
    const float* av = (const float*)d_in[7];

    float* out = (float*)d_out;
    float* att = out + (size_t)NN * DI;

    cudaFuncSetAttribute(k1_mma, cudaFuncAttributeMaxDynamicSharedMemorySize, S_TOTAL);

    k0_init<<<(NN * DI + 255) / 256, 256>>>(out);
    k1_mma<<<296, THREADS, S_TOTAL>>>(x, ei, ea, W1, b1, W2, b2, av);
    k2_exp_denom<<<(NE + 255) / 256, 256>>>(ei);
    k3_scatter<<<(NE * 8 + 255) / 256, 256>>>(ei, out, att);
}